// round 3
// baseline (speedup 1.0000x reference)
#include <cuda_runtime.h>
#include <cuda_bf16.h>

// Problem constants
// 3 modalities, B=16, L=512, D_MODEL=1024, H=8, DK=DV=128
// rows per modality = 16*512 = 8192; total rows = 24576

#define ROWS_PER_MOD 8192
#define TOT_ROWS 24576
#define DM 1024

// ---------------- scratch (device globals; no allocation) ----------------
__device__ float g_Q[3u * 8192u * 1024u];   // also reused as F = O @ w_fc
__device__ float g_K[3u * 8192u * 1024u];
__device__ float g_V[3u * 8192u * 1024u];
__device__ float g_O[3u * 8192u * 1024u];

// ---------------- SGEMM: C[M,1024] = A[M,1024] @ B[1024,1024] ----------------
// 128x128 tile, BK=8, 256 threads, 8x8 per thread (split-tile mapping)
__global__ __launch_bounds__(256, 2)
void sgemm_kernel(const float* __restrict__ A, const float* __restrict__ B,
                  float* __restrict__ C)
{
    __shared__ float As[8][132];   // [kk][m] transposed
    __shared__ float Bs[8][132];   // [kk][n]

    const int tid = threadIdx.x;
    const int tx = tid & 15;
    const int ty = tid >> 4;
    const long n0 = (long)blockIdx.x * 128;
    const long m0 = (long)blockIdx.y * 128;

    const int ar  = tid >> 1;            // 0..127
    const int ac4 = (tid & 1) * 4;       // 0 or 4
    const int br  = tid >> 5;            // 0..7
    const int bc4 = (tid & 31) * 4;      // 0..124

    float acc[8][8];
#pragma unroll
    for (int i = 0; i < 8; i++)
#pragma unroll
        for (int j = 0; j < 8; j++) acc[i][j] = 0.f;

    for (int k0 = 0; k0 < 1024; k0 += 8) {
        float4 av = *(const float4*)(A + (m0 + ar) * 1024 + k0 + ac4);
        float4 bv = *(const float4*)(B + (long)(k0 + br) * 1024 + n0 + bc4);
        __syncthreads();
        As[ac4 + 0][ar] = av.x;
        As[ac4 + 1][ar] = av.y;
        As[ac4 + 2][ar] = av.z;
        As[ac4 + 3][ar] = av.w;
        *(float4*)(&Bs[br][bc4]) = bv;
        __syncthreads();

#pragma unroll
        for (int kk = 0; kk < 8; kk++) {
            float4 a0 = *(const float4*)(&As[kk][ty << 2]);
            float4 a1 = *(const float4*)(&As[kk][64 + (ty << 2)]);
            float4 b0 = *(const float4*)(&Bs[kk][tx << 2]);
            float4 b1 = *(const float4*)(&Bs[kk][64 + (tx << 2)]);
            float a[8] = {a0.x, a0.y, a0.z, a0.w, a1.x, a1.y, a1.z, a1.w};
            float b[8] = {b0.x, b0.y, b0.z, b0.w, b1.x, b1.y, b1.z, b1.w};
#pragma unroll
            for (int i = 0; i < 8; i++)
#pragma unroll
                for (int j = 0; j < 8; j++)
                    acc[i][j] = fmaf(a[i], b[j], acc[i][j]);
        }
    }

#pragma unroll
    for (int i = 0; i < 8; i++) {
        long row = m0 + ((i < 4) ? (ty * 4 + i) : (64 + ty * 4 + (i - 4)));
        float4 c0 = make_float4(acc[i][0], acc[i][1], acc[i][2], acc[i][3]);
        float4 c1 = make_float4(acc[i][4], acc[i][5], acc[i][6], acc[i][7]);
        *(float4*)(C + row * 1024 + n0 + (tx << 2)) = c0;
        *(float4*)(C + row * 1024 + n0 + 64 + (tx << 2)) = c1;
    }
}

// ---------------- Flash attention block kernel ----------------
// grid: (qtile 0..7, h 0..7, m*16+b 0..47), 256 threads
// 64 queries per block, 16 key tiles of 64 over the 1024 concatenated keys.
#define QS_STRIDE 132
#define KT_STRIDE 68     // Kt[128][68]  (K transposed: [d][key])
#define VS_STRIDE 132    // Vs[64][132]
#define PS_STRIDE 68     // Ps[64][68]
#define KV_FLOATS 8704   // max(128*68, 64*132)

__global__ __launch_bounds__(256, 2)
void attn_kernel(const float* __restrict__ Qg, const float* __restrict__ Kg,
                 const float* __restrict__ Vg, float* __restrict__ Og)
{
    extern __shared__ float sm[];
    float* Qs = sm;                        // 64 x 132
    float* KV = sm + 64 * QS_STRIDE;       // union: Kt or Vs
    float* Ps = KV + KV_FLOATS;            // 64 x 68

    const int tid = threadIdx.x;
    const int tx = tid & 15;
    const int ty = tid >> 4;
    const int qtile = blockIdx.x;
    const int h = blockIdx.y;
    const int mb = blockIdx.z;
    const int m = mb >> 4;
    const int b = mb & 15;
    const int o0 = (m == 0) ? 1 : 0;
    const int o1 = (m == 2) ? 1 : 2;

    const float inv_temp = 0.08838834764831845f;  // 1/sqrt(128)

    // load Q tile (scaled)
    const long qbase = ((long)(m * 16 + b) * 512 + qtile * 64) * 1024 + h * 128;
#pragma unroll
    for (int it = 0; it < 8; it++) {
        int idx = it * 256 + tid;
        int r = idx >> 5;
        int c4 = (idx & 31) << 2;
        float4 v = *(const float4*)(Qg + qbase + (long)r * 1024 + c4);
        v.x *= inv_temp; v.y *= inv_temp; v.z *= inv_temp; v.w *= inv_temp;
        *(float4*)(Qs + r * QS_STRIDE + c4) = v;
    }

    float accO[4][8];
    float mrow[4], lrow[4];
#pragma unroll
    for (int i = 0; i < 4; i++) {
        mrow[i] = -1e30f;
        lrow[i] = 0.f;
#pragma unroll
        for (int j = 0; j < 8; j++) accO[i][j] = 0.f;
    }

    __syncthreads();

    for (int t = 0; t < 16; t++) {
        // ---- load K tile transposed: Kt[d][k] ----
#pragma unroll
        for (int it = 0; it < 8; it++) {
            int idx = it * 256 + tid;
            int k = idx & 63;          // per-lane distinct key -> conflict-free STS
            int c4 = (idx >> 6) << 2;  // 0..124
            int kg = t * 64 + k;
            int src = (kg < 512) ? o0 : o1;
            long grow = (long)(src * ROWS_PER_MOD + b * 512 + (kg & 511));
            float4 v = *(const float4*)(Kg + grow * 1024 + h * 128 + c4);
            float* kt = KV + c4 * KT_STRIDE + k;
            kt[0] = v.x;
            kt[KT_STRIDE] = v.y;
            kt[2 * KT_STRIDE] = v.z;
            kt[3 * KT_STRIDE] = v.w;
        }
        __syncthreads();

        // ---- S = (Q/temp) @ K^T  (64x64, 4x4 per thread) ----
        float accS[4][4];
#pragma unroll
        for (int i = 0; i < 4; i++)
#pragma unroll
            for (int j = 0; j < 4; j++) accS[i][j] = 0.f;

#pragma unroll 8
        for (int kk = 0; kk < 128; kk++) {
            const float4 kv = *(const float4*)(KV + kk * KT_STRIDE + (tx << 2));
#pragma unroll
            for (int i = 0; i < 4; i++) {
                const float q = Qs[(ty * 4 + i) * QS_STRIDE + kk];
                accS[i][0] = fmaf(q, kv.x, accS[i][0]);
                accS[i][1] = fmaf(q, kv.y, accS[i][1]);
                accS[i][2] = fmaf(q, kv.z, accS[i][2]);
                accS[i][3] = fmaf(q, kv.w, accS[i][3]);
            }
        }

        // ---- online softmax (per q-row; 16 lanes share a row group) ----
#pragma unroll
        for (int i = 0; i < 4; i++) {
            float tm = fmaxf(fmaxf(accS[i][0], accS[i][1]),
                             fmaxf(accS[i][2], accS[i][3]));
#pragma unroll
            for (int off = 8; off >= 1; off >>= 1)
                tm = fmaxf(tm, __shfl_xor_sync(0xffffffffu, tm, off, 16));
            float newm = fmaxf(mrow[i], tm);
            float scale = __expf(mrow[i] - newm);
            float rsum = 0.f;
#pragma unroll
            for (int j = 0; j < 4; j++) {
                float p = __expf(accS[i][j] - newm);
                accS[i][j] = p;
                rsum += p;
            }
#pragma unroll
            for (int off = 8; off >= 1; off >>= 1)
                rsum += __shfl_xor_sync(0xffffffffu, rsum, off, 16);
            mrow[i] = newm;
            lrow[i] = lrow[i] * scale + rsum;
#pragma unroll
            for (int j = 0; j < 8; j++) accO[i][j] *= scale;
            *(float4*)(Ps + (ty * 4 + i) * PS_STRIDE + (tx << 2)) =
                make_float4(accS[i][0], accS[i][1], accS[i][2], accS[i][3]);
        }
        __syncthreads();

        // ---- load V tile: Vs[k][d] ----
#pragma unroll
        for (int it = 0; it < 8; it++) {
            int idx = it * 256 + tid;
            int k = idx >> 5;
            int c4 = (idx & 31) << 2;
            int kg = t * 64 + k;
            int src = (kg < 512) ? o0 : o1;
            long grow = (long)(src * ROWS_PER_MOD + b * 512 + (kg & 511));
            float4 v = *(const float4*)(Vg + grow * 1024 + h * 128 + c4);
            *(float4*)(KV + k * VS_STRIDE + c4) = v;
        }
        __syncthreads();

        // ---- O += P @ V  (64x128, 4x8 per thread, split cols) ----
#pragma unroll 8
        for (int kk = 0; kk < 64; kk++) {
            const float4 v0 = *(const float4*)(KV + kk * VS_STRIDE + (tx << 2));
            const float4 v1 = *(const float4*)(KV + kk * VS_STRIDE + 64 + (tx << 2));
#pragma unroll
            for (int i = 0; i < 4; i++) {
                const float p = Ps[(ty * 4 + i) * PS_STRIDE + kk];
                accO[i][0] = fmaf(p, v0.x, accO[i][0]);
                accO[i][1] = fmaf(p, v0.y, accO[i][1]);
                accO[i][2] = fmaf(p, v0.z, accO[i][2]);
                accO[i][3] = fmaf(p, v0.w, accO[i][3]);
                accO[i][4] = fmaf(p, v1.x, accO[i][4]);
                accO[i][5] = fmaf(p, v1.y, accO[i][5]);
                accO[i][6] = fmaf(p, v1.z, accO[i][6]);
                accO[i][7] = fmaf(p, v1.w, accO[i][7]);
            }
        }
        __syncthreads();
    }

    // ---- finalize + store O in [row, h*128+d] layout ----
    const long obase = ((long)(m * 16 + b) * 512 + qtile * 64) * 1024 + h * 128;
#pragma unroll
    for (int i = 0; i < 4; i++) {
        float inv = 1.f / lrow[i];
        int r = ty * 4 + i;
        float4 w0 = make_float4(accO[i][0] * inv, accO[i][1] * inv,
                                accO[i][2] * inv, accO[i][3] * inv);
        float4 w1 = make_float4(accO[i][4] * inv, accO[i][5] * inv,
                                accO[i][6] * inv, accO[i][7] * inv);
        *(float4*)(Og + obase + (long)r * 1024 + (tx << 2)) = w0;
        *(float4*)(Og + obase + (long)r * 1024 + 64 + (tx << 2)) = w1;
    }
}

// ---------------- fused residual + LayerNorm ----------------
// one block (256 thr) per row of 1024
__global__ __launch_bounds__(256)
void ln_kernel(const float* __restrict__ F,
               const float* __restrict__ x_t, const float* __restrict__ x_a,
               const float* __restrict__ x_v,
               const float* __restrict__ g, const float* __restrict__ bb,
               float* __restrict__ out)
{
    const long row = blockIdx.x;
    const int m = (int)(row >> 13);  // /8192
    const float* X = (m == 0) ? x_t : ((m == 1) ? x_a : x_v);
    const long xoff = (row & 8191) * 1024;
    const long foff = row * 1024;
    const int tid = threadIdx.x;

    float vals[4];
    float s = 0.f, s2 = 0.f;
#pragma unroll
    for (int u = 0; u < 4; u++) {
        int c = tid + u * 256;
        float v = F[foff + c] + X[xoff + c];
        vals[u] = v;
        s += v;
        s2 += v * v;
    }
#pragma unroll
    for (int off = 16; off >= 1; off >>= 1) {
        s += __shfl_xor_sync(0xffffffffu, s, off);
        s2 += __shfl_xor_sync(0xffffffffu, s2, off);
    }
    __shared__ float ss[8], ss2[8];
    const int w = tid >> 5, l = tid & 31;
    if (l == 0) { ss[w] = s; ss2[w] = s2; }
    __syncthreads();
    if (w == 0) {
        s = (l < 8) ? ss[l] : 0.f;
        s2 = (l < 8) ? ss2[l] : 0.f;
#pragma unroll
        for (int off = 4; off >= 1; off >>= 1) {
            s += __shfl_xor_sync(0xffffffffu, s, off);
            s2 += __shfl_xor_sync(0xffffffffu, s2, off);
        }
        if (l == 0) {
            float mu = s * (1.f / 1024.f);
            float var = s2 * (1.f / 1024.f) - mu * mu;
            ss[0] = mu;
            ss2[0] = rsqrtf(var + 1e-6f);
        }
    }
    __syncthreads();
    const float mu = ss[0], rstd = ss2[0];
#pragma unroll
    for (int u = 0; u < 4; u++) {
        int c = tid + u * 256;
        out[foff + c] = (vals[u] - mu) * rstd * g[c] + bb[c];
    }
}

// ---------------- launch ----------------
extern "C" void kernel_launch(void* const* d_in, const int* in_sizes, int n_in,
                              void* d_out, int out_size)
{
    const float* x[3] = {(const float*)d_in[0], (const float*)d_in[1],
                         (const float*)d_in[2]};
    const float* w_qs = (const float*)d_in[3];
    const float* w_ks = (const float*)d_in[4];
    const float* w_vs = (const float*)d_in[5];
    const float* w_fc = (const float*)d_in[6];
    const float* ln_g = (const float*)d_in[7];
    const float* ln_b = (const float*)d_in[8];
    float* out = (float*)d_out;

    float *Q, *K, *V, *O;
    cudaGetSymbolAddress((void**)&Q, g_Q);
    cudaGetSymbolAddress((void**)&K, g_K);
    cudaGetSymbolAddress((void**)&V, g_V);
    cudaGetSymbolAddress((void**)&O, g_O);

    const int attn_smem = (64 * QS_STRIDE + KV_FLOATS + 64 * PS_STRIDE) * 4;  // 86016
    cudaFuncSetAttribute(attn_kernel,
                         cudaFuncAttributeMaxDynamicSharedMemorySize, attn_smem);

    dim3 gproj(1024 / 128, ROWS_PER_MOD / 128);  // (8, 64)
    for (int m = 0; m < 3; m++) {
        sgemm_kernel<<<gproj, 256>>>(x[m], w_qs, Q + (long)m * ROWS_PER_MOD * 1024);
        sgemm_kernel<<<gproj, 256>>>(x[m], w_ks, K + (long)m * ROWS_PER_MOD * 1024);
        sgemm_kernel<<<gproj, 256>>>(x[m], w_vs, V + (long)m * ROWS_PER_MOD * 1024);
    }

    attn_kernel<<<dim3(8, 8, 48), 256, attn_smem>>>(Q, K, V, O);

    // F = O @ w_fc (reuse g_Q as F)
    sgemm_kernel<<<dim3(1024 / 128, TOT_ROWS / 128), 256>>>(O, w_fc, Q);

    ln_kernel<<<TOT_ROWS, 256>>>(Q, x[0], x[1], x[2], ln_g, ln_b, out);
}

// round 4
// speedup vs baseline: 1.0001x; 1.0001x over previous
#include <cuda_runtime.h>
#include <cuda_bf16.h>

// Problem constants
// 3 modalities, B=16, L=512, D_MODEL=1024, H=8, DK=DV=128
// rows per modality = 16*512 = 8192; total rows = 24576

#define ROWS_PER_MOD 8192
#define TOT_ROWS 24576
#define DM 1024

// ---------------- scratch (device globals; no allocation) ----------------
__device__ float g_Q[3u * 8192u * 1024u];   // also reused as F = O @ w_fc
__device__ float g_K[3u * 8192u * 1024u];
__device__ float g_V[3u * 8192u * 1024u];
__device__ float g_O[3u * 8192u * 1024u];

// ---------------- SGEMM: C[M,1024] = A[M,1024] @ B[1024,1024] ----------------
// 128x128 tile, BK=8, 256 threads, 8x8 per thread (split-tile mapping)
__global__ __launch_bounds__(256, 2)
void sgemm_kernel(const float* __restrict__ A, const float* __restrict__ B,
                  float* __restrict__ C)
{
    __shared__ float As[8][132];   // [kk][m] transposed
    __shared__ float Bs[8][132];   // [kk][n]

    const int tid = threadIdx.x;
    const int tx = tid & 15;
    const int ty = tid >> 4;
    const long n0 = (long)blockIdx.x * 128;
    const long m0 = (long)blockIdx.y * 128;

    const int ar  = tid >> 1;            // 0..127
    const int ac4 = (tid & 1) * 4;       // 0 or 4
    const int br  = tid >> 5;            // 0..7
    const int bc4 = (tid & 31) * 4;      // 0..124

    float acc[8][8];
#pragma unroll
    for (int i = 0; i < 8; i++)
#pragma unroll
        for (int j = 0; j < 8; j++) acc[i][j] = 0.f;

    for (int k0 = 0; k0 < 1024; k0 += 8) {
        float4 av = *(const float4*)(A + (m0 + ar) * 1024 + k0 + ac4);
        float4 bv = *(const float4*)(B + (long)(k0 + br) * 1024 + n0 + bc4);
        __syncthreads();
        As[ac4 + 0][ar] = av.x;
        As[ac4 + 1][ar] = av.y;
        As[ac4 + 2][ar] = av.z;
        As[ac4 + 3][ar] = av.w;
        *(float4*)(&Bs[br][bc4]) = bv;
        __syncthreads();

#pragma unroll
        for (int kk = 0; kk < 8; kk++) {
            float4 a0 = *(const float4*)(&As[kk][ty << 2]);
            float4 a1 = *(const float4*)(&As[kk][64 + (ty << 2)]);
            float4 b0 = *(const float4*)(&Bs[kk][tx << 2]);
            float4 b1 = *(const float4*)(&Bs[kk][64 + (tx << 2)]);
            float a[8] = {a0.x, a0.y, a0.z, a0.w, a1.x, a1.y, a1.z, a1.w};
            float b[8] = {b0.x, b0.y, b0.z, b0.w, b1.x, b1.y, b1.z, b1.w};
#pragma unroll
            for (int i = 0; i < 8; i++)
#pragma unroll
                for (int j = 0; j < 8; j++)
                    acc[i][j] = fmaf(a[i], b[j], acc[i][j]);
        }
    }

#pragma unroll
    for (int i = 0; i < 8; i++) {
        long row = m0 + ((i < 4) ? (ty * 4 + i) : (64 + ty * 4 + (i - 4)));
        float4 c0 = make_float4(acc[i][0], acc[i][1], acc[i][2], acc[i][3]);
        float4 c1 = make_float4(acc[i][4], acc[i][5], acc[i][6], acc[i][7]);
        *(float4*)(C + row * 1024 + n0 + (tx << 2)) = c0;
        *(float4*)(C + row * 1024 + n0 + 64 + (tx << 2)) = c1;
    }
}

// ---------------- Flash attention block kernel ----------------
// grid: (qtile 0..7, h 0..7, m*16+b 0..47), 256 threads
// 64 queries per block, 16 key tiles of 64 over the 1024 concatenated keys.
#define QS_STRIDE 132
#define KT_STRIDE 68     // Kt[128][68]  (K transposed: [d][key])
#define VS_STRIDE 132    // Vs[64][132]
#define PS_STRIDE 68     // Ps[64][68]
#define KV_FLOATS 8704   // max(128*68, 64*132)

__global__ __launch_bounds__(256, 2)
void attn_kernel(const float* __restrict__ Qg, const float* __restrict__ Kg,
                 const float* __restrict__ Vg, float* __restrict__ Og)
{
    extern __shared__ float sm[];
    float* Qs = sm;                        // 64 x 132
    float* KV = sm + 64 * QS_STRIDE;       // union: Kt or Vs
    float* Ps = KV + KV_FLOATS;            // 64 x 68

    const int tid = threadIdx.x;
    const int tx = tid & 15;
    const int ty = tid >> 4;
    const int qtile = blockIdx.x;
    const int h = blockIdx.y;
    const int mb = blockIdx.z;
    const int m = mb >> 4;
    const int b = mb & 15;
    const int o0 = (m == 0) ? 1 : 0;
    const int o1 = (m == 2) ? 1 : 2;

    const float inv_temp = 0.08838834764831845f;  // 1/sqrt(128)

    // load Q tile (scaled)
    const long qbase = ((long)(m * 16 + b) * 512 + qtile * 64) * 1024 + h * 128;
#pragma unroll
    for (int it = 0; it < 8; it++) {
        int idx = it * 256 + tid;
        int r = idx >> 5;
        int c4 = (idx & 31) << 2;
        float4 v = *(const float4*)(Qg + qbase + (long)r * 1024 + c4);
        v.x *= inv_temp; v.y *= inv_temp; v.z *= inv_temp; v.w *= inv_temp;
        *(float4*)(Qs + r * QS_STRIDE + c4) = v;
    }

    float accO[4][8];
    float mrow[4], lrow[4];
#pragma unroll
    for (int i = 0; i < 4; i++) {
        mrow[i] = -1e30f;
        lrow[i] = 0.f;
#pragma unroll
        for (int j = 0; j < 8; j++) accO[i][j] = 0.f;
    }

    __syncthreads();

    for (int t = 0; t < 16; t++) {
        // ---- load K tile transposed: Kt[d][k] ----
#pragma unroll
        for (int it = 0; it < 8; it++) {
            int idx = it * 256 + tid;
            int k = idx & 63;          // per-lane distinct key -> conflict-free STS
            int c4 = (idx >> 6) << 2;  // 0..124
            int kg = t * 64 + k;
            int src = (kg < 512) ? o0 : o1;
            long grow = (long)(src * ROWS_PER_MOD + b * 512 + (kg & 511));
            float4 v = *(const float4*)(Kg + grow * 1024 + h * 128 + c4);
            float* kt = KV + c4 * KT_STRIDE + k;
            kt[0] = v.x;
            kt[KT_STRIDE] = v.y;
            kt[2 * KT_STRIDE] = v.z;
            kt[3 * KT_STRIDE] = v.w;
        }
        __syncthreads();

        // ---- S = (Q/temp) @ K^T  (64x64, 4x4 per thread) ----
        float accS[4][4];
#pragma unroll
        for (int i = 0; i < 4; i++)
#pragma unroll
            for (int j = 0; j < 4; j++) accS[i][j] = 0.f;

#pragma unroll 8
        for (int kk = 0; kk < 128; kk++) {
            const float4 kv = *(const float4*)(KV + kk * KT_STRIDE + (tx << 2));
#pragma unroll
            for (int i = 0; i < 4; i++) {
                const float q = Qs[(ty * 4 + i) * QS_STRIDE + kk];
                accS[i][0] = fmaf(q, kv.x, accS[i][0]);
                accS[i][1] = fmaf(q, kv.y, accS[i][1]);
                accS[i][2] = fmaf(q, kv.z, accS[i][2]);
                accS[i][3] = fmaf(q, kv.w, accS[i][3]);
            }
        }

        // ---- online softmax (per q-row; 16 lanes share a row group) ----
#pragma unroll
        for (int i = 0; i < 4; i++) {
            float tm = fmaxf(fmaxf(accS[i][0], accS[i][1]),
                             fmaxf(accS[i][2], accS[i][3]));
#pragma unroll
            for (int off = 8; off >= 1; off >>= 1)
                tm = fmaxf(tm, __shfl_xor_sync(0xffffffffu, tm, off, 16));
            float newm = fmaxf(mrow[i], tm);
            float scale = __expf(mrow[i] - newm);
            float rsum = 0.f;
#pragma unroll
            for (int j = 0; j < 4; j++) {
                float p = __expf(accS[i][j] - newm);
                accS[i][j] = p;
                rsum += p;
            }
#pragma unroll
            for (int off = 8; off >= 1; off >>= 1)
                rsum += __shfl_xor_sync(0xffffffffu, rsum, off, 16);
            mrow[i] = newm;
            lrow[i] = lrow[i] * scale + rsum;
#pragma unroll
            for (int j = 0; j < 8; j++) accO[i][j] *= scale;
            *(float4*)(Ps + (ty * 4 + i) * PS_STRIDE + (tx << 2)) =
                make_float4(accS[i][0], accS[i][1], accS[i][2], accS[i][3]);
        }
        __syncthreads();

        // ---- load V tile: Vs[k][d] ----
#pragma unroll
        for (int it = 0; it < 8; it++) {
            int idx = it * 256 + tid;
            int k = idx >> 5;
            int c4 = (idx & 31) << 2;
            int kg = t * 64 + k;
            int src = (kg < 512) ? o0 : o1;
            long grow = (long)(src * ROWS_PER_MOD + b * 512 + (kg & 511));
            float4 v = *(const float4*)(Vg + grow * 1024 + h * 128 + c4);
            *(float4*)(KV + k * VS_STRIDE + c4) = v;
        }
        __syncthreads();

        // ---- O += P @ V  (64x128, 4x8 per thread, split cols) ----
#pragma unroll 8
        for (int kk = 0; kk < 64; kk++) {
            const float4 v0 = *(const float4*)(KV + kk * VS_STRIDE + (tx << 2));
            const float4 v1 = *(const float4*)(KV + kk * VS_STRIDE + 64 + (tx << 2));
#pragma unroll
            for (int i = 0; i < 4; i++) {
                const float p = Ps[(ty * 4 + i) * PS_STRIDE + kk];
                accO[i][0] = fmaf(p, v0.x, accO[i][0]);
                accO[i][1] = fmaf(p, v0.y, accO[i][1]);
                accO[i][2] = fmaf(p, v0.z, accO[i][2]);
                accO[i][3] = fmaf(p, v0.w, accO[i][3]);
                accO[i][4] = fmaf(p, v1.x, accO[i][4]);
                accO[i][5] = fmaf(p, v1.y, accO[i][5]);
                accO[i][6] = fmaf(p, v1.z, accO[i][6]);
                accO[i][7] = fmaf(p, v1.w, accO[i][7]);
            }
        }
        __syncthreads();
    }

    // ---- finalize + store O in [row, h*128+d] layout ----
    const long obase = ((long)(m * 16 + b) * 512 + qtile * 64) * 1024 + h * 128;
#pragma unroll
    for (int i = 0; i < 4; i++) {
        float inv = 1.f / lrow[i];
        int r = ty * 4 + i;
        float4 w0 = make_float4(accO[i][0] * inv, accO[i][1] * inv,
                                accO[i][2] * inv, accO[i][3] * inv);
        float4 w1 = make_float4(accO[i][4] * inv, accO[i][5] * inv,
                                accO[i][6] * inv, accO[i][7] * inv);
        *(float4*)(Og + obase + (long)r * 1024 + (tx << 2)) = w0;
        *(float4*)(Og + obase + (long)r * 1024 + 64 + (tx << 2)) = w1;
    }
}

// ---------------- fused residual + LayerNorm ----------------
// one block (256 thr) per row of 1024
__global__ __launch_bounds__(256)
void ln_kernel(const float* __restrict__ F,
               const float* __restrict__ x_t, const float* __restrict__ x_a,
               const float* __restrict__ x_v,
               const float* __restrict__ g, const float* __restrict__ bb,
               float* __restrict__ out)
{
    const long row = blockIdx.x;
    const int m = (int)(row >> 13);  // /8192
    const float* X = (m == 0) ? x_t : ((m == 1) ? x_a : x_v);
    const long xoff = (row & 8191) * 1024;
    const long foff = row * 1024;
    const int tid = threadIdx.x;

    float vals[4];
    float s = 0.f, s2 = 0.f;
#pragma unroll
    for (int u = 0; u < 4; u++) {
        int c = tid + u * 256;
        float v = F[foff + c] + X[xoff + c];
        vals[u] = v;
        s += v;
        s2 += v * v;
    }
#pragma unroll
    for (int off = 16; off >= 1; off >>= 1) {
        s += __shfl_xor_sync(0xffffffffu, s, off);
        s2 += __shfl_xor_sync(0xffffffffu, s2, off);
    }
    __shared__ float ss[8], ss2[8];
    const int w = tid >> 5, l = tid & 31;
    if (l == 0) { ss[w] = s; ss2[w] = s2; }
    __syncthreads();
    if (w == 0) {
        s = (l < 8) ? ss[l] : 0.f;
        s2 = (l < 8) ? ss2[l] : 0.f;
#pragma unroll
        for (int off = 4; off >= 1; off >>= 1) {
            s += __shfl_xor_sync(0xffffffffu, s, off);
            s2 += __shfl_xor_sync(0xffffffffu, s2, off);
        }
        if (l == 0) {
            float mu = s * (1.f / 1024.f);
            float var = s2 * (1.f / 1024.f) - mu * mu;
            ss[0] = mu;
            ss2[0] = rsqrtf(var + 1e-6f);
        }
    }
    __syncthreads();
    const float mu = ss[0], rstd = ss2[0];
#pragma unroll
    for (int u = 0; u < 4; u++) {
        int c = tid + u * 256;
        out[foff + c] = (vals[u] - mu) * rstd * g[c] + bb[c];
    }
}

// ---------------- launch ----------------
extern "C" void kernel_launch(void* const* d_in, const int* in_sizes, int n_in,
                              void* d_out, int out_size)
{
    const float* x[3] = {(const float*)d_in[0], (const float*)d_in[1],
                         (const float*)d_in[2]};
    const float* w_qs = (const float*)d_in[3];
    const float* w_ks = (const float*)d_in[4];
    const float* w_vs = (const float*)d_in[5];
    const float* w_fc = (const float*)d_in[6];
    const float* ln_g = (const float*)d_in[7];
    const float* ln_b = (const float*)d_in[8];
    float* out = (float*)d_out;

    float *Q, *K, *V, *O;
    cudaGetSymbolAddress((void**)&Q, g_Q);
    cudaGetSymbolAddress((void**)&K, g_K);
    cudaGetSymbolAddress((void**)&V, g_V);
    cudaGetSymbolAddress((void**)&O, g_O);

    const int attn_smem = (64 * QS_STRIDE + KV_FLOATS + 64 * PS_STRIDE) * 4;  // 86016
    cudaFuncSetAttribute(attn_kernel,
                         cudaFuncAttributeMaxDynamicSharedMemorySize, attn_smem);

    dim3 gproj(1024 / 128, ROWS_PER_MOD / 128);  // (8, 64)
    for (int m = 0; m < 3; m++) {
        sgemm_kernel<<<gproj, 256>>>(x[m], w_qs, Q + (long)m * ROWS_PER_MOD * 1024);
        sgemm_kernel<<<gproj, 256>>>(x[m], w_ks, K + (long)m * ROWS_PER_MOD * 1024);
        sgemm_kernel<<<gproj, 256>>>(x[m], w_vs, V + (long)m * ROWS_PER_MOD * 1024);
    }

    attn_kernel<<<dim3(8, 8, 48), 256, attn_smem>>>(Q, K, V, O);

    // F = O @ w_fc (reuse g_Q as F)
    sgemm_kernel<<<dim3(1024 / 128, TOT_ROWS / 128), 256>>>(O, w_fc, Q);

    ln_kernel<<<TOT_ROWS, 256>>>(Q, x[0], x[1], x[2], ln_g, ln_b, out);
}

// round 7
// speedup vs baseline: 1.0006x; 1.0005x over previous
#include <cuda_runtime.h>
#include <cuda_bf16.h>

// Problem constants
// 3 modalities, B=16, L=512, D_MODEL=1024, H=8, DK=DV=128
// rows per modality = 16*512 = 8192; total rows = 24576

#define ROWS_PER_MOD 8192
#define TOT_ROWS 24576
#define DM 1024

// ---------------- scratch (device globals; no allocation) ----------------
__device__ float g_Q[3u * 8192u * 1024u];   // also reused as F = O @ w_fc
__device__ float g_K[3u * 8192u * 1024u];
__device__ float g_V[3u * 8192u * 1024u];
__device__ float g_O[3u * 8192u * 1024u];

// ---------------- SGEMM: C[M,1024] = A[M,1024] @ B[1024,1024] ----------------
// 128x128 tile, BK=8, 256 threads, 8x8 per thread (split-tile mapping)
__global__ __launch_bounds__(256, 2)
void sgemm_kernel(const float* __restrict__ A, const float* __restrict__ B,
                  float* __restrict__ C)
{
    __shared__ float As[8][132];   // [kk][m] transposed
    __shared__ float Bs[8][132];   // [kk][n]

    const int tid = threadIdx.x;
    const int tx = tid & 15;
    const int ty = tid >> 4;
    const long n0 = (long)blockIdx.x * 128;
    const long m0 = (long)blockIdx.y * 128;

    const int ar  = tid >> 1;            // 0..127
    const int ac4 = (tid & 1) * 4;       // 0 or 4
    const int br  = tid >> 5;            // 0..7
    const int bc4 = (tid & 31) * 4;      // 0..124

    float acc[8][8];
#pragma unroll
    for (int i = 0; i < 8; i++)
#pragma unroll
        for (int j = 0; j < 8; j++) acc[i][j] = 0.f;

    for (int k0 = 0; k0 < 1024; k0 += 8) {
        float4 av = *(const float4*)(A + (m0 + ar) * 1024 + k0 + ac4);
        float4 bv = *(const float4*)(B + (long)(k0 + br) * 1024 + n0 + bc4);
        __syncthreads();
        As[ac4 + 0][ar] = av.x;
        As[ac4 + 1][ar] = av.y;
        As[ac4 + 2][ar] = av.z;
        As[ac4 + 3][ar] = av.w;
        *(float4*)(&Bs[br][bc4]) = bv;
        __syncthreads();

#pragma unroll
        for (int kk = 0; kk < 8; kk++) {
            float4 a0 = *(const float4*)(&As[kk][ty << 2]);
            float4 a1 = *(const float4*)(&As[kk][64 + (ty << 2)]);
            float4 b0 = *(const float4*)(&Bs[kk][tx << 2]);
            float4 b1 = *(const float4*)(&Bs[kk][64 + (tx << 2)]);
            float a[8] = {a0.x, a0.y, a0.z, a0.w, a1.x, a1.y, a1.z, a1.w};
            float b[8] = {b0.x, b0.y, b0.z, b0.w, b1.x, b1.y, b1.z, b1.w};
#pragma unroll
            for (int i = 0; i < 8; i++)
#pragma unroll
                for (int j = 0; j < 8; j++)
                    acc[i][j] = fmaf(a[i], b[j], acc[i][j]);
        }
    }

#pragma unroll
    for (int i = 0; i < 8; i++) {
        long row = m0 + ((i < 4) ? (ty * 4 + i) : (64 + ty * 4 + (i - 4)));
        float4 c0 = make_float4(acc[i][0], acc[i][1], acc[i][2], acc[i][3]);
        float4 c1 = make_float4(acc[i][4], acc[i][5], acc[i][6], acc[i][7]);
        *(float4*)(C + row * 1024 + n0 + (tx << 2)) = c0;
        *(float4*)(C + row * 1024 + n0 + 64 + (tx << 2)) = c1;
    }
}

// ---------------- Flash attention block kernel ----------------
// grid: (qtile 0..7, h 0..7, m*16+b 0..47), 256 threads
// 64 queries per block, 16 key tiles of 64 over the 1024 concatenated keys.
#define QS_STRIDE 132
#define KT_STRIDE 68     // Kt[128][68]  (K transposed: [d][key])
#define VS_STRIDE 132    // Vs[64][132]
#define PS_STRIDE 68     // Ps[64][68]
#define KV_FLOATS 8704   // max(128*68, 64*132)

__global__ __launch_bounds__(256, 2)
void attn_kernel(const float* __restrict__ Qg, const float* __restrict__ Kg,
                 const float* __restrict__ Vg, float* __restrict__ Og)
{
    extern __shared__ float sm[];
    float* Qs = sm;                        // 64 x 132
    float* KV = sm + 64 * QS_STRIDE;       // union: Kt or Vs
    float* Ps = KV + KV_FLOATS;            // 64 x 68

    const int tid = threadIdx.x;
    const int tx = tid & 15;
    const int ty = tid >> 4;
    const int qtile = blockIdx.x;
    const int h = blockIdx.y;
    const int mb = blockIdx.z;
    const int m = mb >> 4;
    const int b = mb & 15;
    const int o0 = (m == 0) ? 1 : 0;
    const int o1 = (m == 2) ? 1 : 2;

    const float inv_temp = 0.08838834764831845f;  // 1/sqrt(128)

    // load Q tile (scaled)
    const long qbase = ((long)(m * 16 + b) * 512 + qtile * 64) * 1024 + h * 128;
#pragma unroll
    for (int it = 0; it < 8; it++) {
        int idx = it * 256 + tid;
        int r = idx >> 5;
        int c4 = (idx & 31) << 2;
        float4 v = *(const float4*)(Qg + qbase + (long)r * 1024 + c4);
        v.x *= inv_temp; v.y *= inv_temp; v.z *= inv_temp; v.w *= inv_temp;
        *(float4*)(Qs + r * QS_STRIDE + c4) = v;
    }

    float accO[4][8];
    float mrow[4], lrow[4];
#pragma unroll
    for (int i = 0; i < 4; i++) {
        mrow[i] = -1e30f;
        lrow[i] = 0.f;
#pragma unroll
        for (int j = 0; j < 8; j++) accO[i][j] = 0.f;
    }

    __syncthreads();

    for (int t = 0; t < 16; t++) {
        // ---- load K tile transposed: Kt[d][k] ----
#pragma unroll
        for (int it = 0; it < 8; it++) {
            int idx = it * 256 + tid;
            int k = idx & 63;          // per-lane distinct key -> conflict-free STS
            int c4 = (idx >> 6) << 2;  // 0..124
            int kg = t * 64 + k;
            int src = (kg < 512) ? o0 : o1;
            long grow = (long)(src * ROWS_PER_MOD + b * 512 + (kg & 511));
            float4 v = *(const float4*)(Kg + grow * 1024 + h * 128 + c4);
            float* kt = KV + c4 * KT_STRIDE + k;
            kt[0] = v.x;
            kt[KT_STRIDE] = v.y;
            kt[2 * KT_STRIDE] = v.z;
            kt[3 * KT_STRIDE] = v.w;
        }
        __syncthreads();

        // ---- S = (Q/temp) @ K^T  (64x64, 4x4 per thread) ----
        float accS[4][4];
#pragma unroll
        for (int i = 0; i < 4; i++)
#pragma unroll
            for (int j = 0; j < 4; j++) accS[i][j] = 0.f;

#pragma unroll 8
        for (int kk = 0; kk < 128; kk++) {
            const float4 kv = *(const float4*)(KV + kk * KT_STRIDE + (tx << 2));
#pragma unroll
            for (int i = 0; i < 4; i++) {
                const float q = Qs[(ty * 4 + i) * QS_STRIDE + kk];
                accS[i][0] = fmaf(q, kv.x, accS[i][0]);
                accS[i][1] = fmaf(q, kv.y, accS[i][1]);
                accS[i][2] = fmaf(q, kv.z, accS[i][2]);
                accS[i][3] = fmaf(q, kv.w, accS[i][3]);
            }
        }

        // ---- online softmax (per q-row; 16 lanes share a row group) ----
#pragma unroll
        for (int i = 0; i < 4; i++) {
            float tm = fmaxf(fmaxf(accS[i][0], accS[i][1]),
                             fmaxf(accS[i][2], accS[i][3]));
#pragma unroll
            for (int off = 8; off >= 1; off >>= 1)
                tm = fmaxf(tm, __shfl_xor_sync(0xffffffffu, tm, off, 16));
            float newm = fmaxf(mrow[i], tm);
            float scale = __expf(mrow[i] - newm);
            float rsum = 0.f;
#pragma unroll
            for (int j = 0; j < 4; j++) {
                float p = __expf(accS[i][j] - newm);
                accS[i][j] = p;
                rsum += p;
            }
#pragma unroll
            for (int off = 8; off >= 1; off >>= 1)
                rsum += __shfl_xor_sync(0xffffffffu, rsum, off, 16);
            mrow[i] = newm;
            lrow[i] = lrow[i] * scale + rsum;
#pragma unroll
            for (int j = 0; j < 8; j++) accO[i][j] *= scale;
            *(float4*)(Ps + (ty * 4 + i) * PS_STRIDE + (tx << 2)) =
                make_float4(accS[i][0], accS[i][1], accS[i][2], accS[i][3]);
        }
        __syncthreads();

        // ---- load V tile: Vs[k][d] ----
#pragma unroll
        for (int it = 0; it < 8; it++) {
            int idx = it * 256 + tid;
            int k = idx >> 5;
            int c4 = (idx & 31) << 2;
            int kg = t * 64 + k;
            int src = (kg < 512) ? o0 : o1;
            long grow = (long)(src * ROWS_PER_MOD + b * 512 + (kg & 511));
            float4 v = *(const float4*)(Vg + grow * 1024 + h * 128 + c4);
            *(float4*)(KV + k * VS_STRIDE + c4) = v;
        }
        __syncthreads();

        // ---- O += P @ V  (64x128, 4x8 per thread, split cols) ----
#pragma unroll 8
        for (int kk = 0; kk < 64; kk++) {
            const float4 v0 = *(const float4*)(KV + kk * VS_STRIDE + (tx << 2));
            const float4 v1 = *(const float4*)(KV + kk * VS_STRIDE + 64 + (tx << 2));
#pragma unroll
            for (int i = 0; i < 4; i++) {
                const float p = Ps[(ty * 4 + i) * PS_STRIDE + kk];
                accO[i][0] = fmaf(p, v0.x, accO[i][0]);
                accO[i][1] = fmaf(p, v0.y, accO[i][1]);
                accO[i][2] = fmaf(p, v0.z, accO[i][2]);
                accO[i][3] = fmaf(p, v0.w, accO[i][3]);
                accO[i][4] = fmaf(p, v1.x, accO[i][4]);
                accO[i][5] = fmaf(p, v1.y, accO[i][5]);
                accO[i][6] = fmaf(p, v1.z, accO[i][6]);
                accO[i][7] = fmaf(p, v1.w, accO[i][7]);
            }
        }
        __syncthreads();
    }

    // ---- finalize + store O in [row, h*128+d] layout ----
    const long obase = ((long)(m * 16 + b) * 512 + qtile * 64) * 1024 + h * 128;
#pragma unroll
    for (int i = 0; i < 4; i++) {
        float inv = 1.f / lrow[i];
        int r = ty * 4 + i;
        float4 w0 = make_float4(accO[i][0] * inv, accO[i][1] * inv,
                                accO[i][2] * inv, accO[i][3] * inv);
        float4 w1 = make_float4(accO[i][4] * inv, accO[i][5] * inv,
                                accO[i][6] * inv, accO[i][7] * inv);
        *(float4*)(Og + obase + (long)r * 1024 + (tx << 2)) = w0;
        *(float4*)(Og + obase + (long)r * 1024 + 64 + (tx << 2)) = w1;
    }
}

// ---------------- fused residual + LayerNorm ----------------
// one block (256 thr) per row of 1024
__global__ __launch_bounds__(256)
void ln_kernel(const float* __restrict__ F,
               const float* __restrict__ x_t, const float* __restrict__ x_a,
               const float* __restrict__ x_v,
               const float* __restrict__ g, const float* __restrict__ bb,
               float* __restrict__ out)
{
    const long row = blockIdx.x;
    const int m = (int)(row >> 13);  // /8192
    const float* X = (m == 0) ? x_t : ((m == 1) ? x_a : x_v);
    const long xoff = (row & 8191) * 1024;
    const long foff = row * 1024;
    const int tid = threadIdx.x;

    float vals[4];
    float s = 0.f, s2 = 0.f;
#pragma unroll
    for (int u = 0; u < 4; u++) {
        int c = tid + u * 256;
        float v = F[foff + c] + X[xoff + c];
        vals[u] = v;
        s += v;
        s2 += v * v;
    }
#pragma unroll
    for (int off = 16; off >= 1; off >>= 1) {
        s += __shfl_xor_sync(0xffffffffu, s, off);
        s2 += __shfl_xor_sync(0xffffffffu, s2, off);
    }
    __shared__ float ss[8], ss2[8];
    const int w = tid >> 5, l = tid & 31;
    if (l == 0) { ss[w] = s; ss2[w] = s2; }
    __syncthreads();
    if (w == 0) {
        s = (l < 8) ? ss[l] : 0.f;
        s2 = (l < 8) ? ss2[l] : 0.f;
#pragma unroll
        for (int off = 4; off >= 1; off >>= 1) {
            s += __shfl_xor_sync(0xffffffffu, s, off);
            s2 += __shfl_xor_sync(0xffffffffu, s2, off);
        }
        if (l == 0) {
            float mu = s * (1.f / 1024.f);
            float var = s2 * (1.f / 1024.f) - mu * mu;
            ss[0] = mu;
            ss2[0] = rsqrtf(var + 1e-6f);
        }
    }
    __syncthreads();
    const float mu = ss[0], rstd = ss2[0];
#pragma unroll
    for (int u = 0; u < 4; u++) {
        int c = tid + u * 256;
        out[foff + c] = (vals[u] - mu) * rstd * g[c] + bb[c];
    }
}

// ---------------- launch ----------------
extern "C" void kernel_launch(void* const* d_in, const int* in_sizes, int n_in,
                              void* d_out, int out_size)
{
    const float* x[3] = {(const float*)d_in[0], (const float*)d_in[1],
                         (const float*)d_in[2]};
    const float* w_qs = (const float*)d_in[3];
    const float* w_ks = (const float*)d_in[4];
    const float* w_vs = (const float*)d_in[5];
    const float* w_fc = (const float*)d_in[6];
    const float* ln_g = (const float*)d_in[7];
    const float* ln_b = (const float*)d_in[8];
    float* out = (float*)d_out;

    float *Q, *K, *V, *O;
    cudaGetSymbolAddress((void**)&Q, g_Q);
    cudaGetSymbolAddress((void**)&K, g_K);
    cudaGetSymbolAddress((void**)&V, g_V);
    cudaGetSymbolAddress((void**)&O, g_O);

    const int attn_smem = (64 * QS_STRIDE + KV_FLOATS + 64 * PS_STRIDE) * 4;  // 86016
    cudaFuncSetAttribute(attn_kernel,
                         cudaFuncAttributeMaxDynamicSharedMemorySize, attn_smem);

    dim3 gproj(1024 / 128, ROWS_PER_MOD / 128);  // (8, 64)
    for (int m = 0; m < 3; m++) {
        sgemm_kernel<<<gproj, 256>>>(x[m], w_qs, Q + (long)m * ROWS_PER_MOD * 1024);
        sgemm_kernel<<<gproj, 256>>>(x[m], w_ks, K + (long)m * ROWS_PER_MOD * 1024);
        sgemm_kernel<<<gproj, 256>>>(x[m], w_vs, V + (long)m * ROWS_PER_MOD * 1024);
    }

    attn_kernel<<<dim3(8, 8, 48), 256, attn_smem>>>(Q, K, V, O);

    // F = O @ w_fc (reuse g_Q as F)
    sgemm_kernel<<<dim3(1024 / 128, TOT_ROWS / 128), 256>>>(O, w_fc, Q);

    ln_kernel<<<TOT_ROWS, 256>>>(Q, x[0], x[1], x[2], ln_g, ln_b, out);
}